// round 10
// baseline (speedup 1.0000x reference)
#include <cuda_runtime.h>
#include <cuda_bf16.h>
#include <math.h>
#include <stdint.h>
#include <string.h>

#define EMBED 512
#define NHEADS 8
#define HD 64
#define BATCH 2
#define SEQ 4096
#define MTOT (BATCH*SEQ)

// bf16 hi/lo split tensors.
__device__ __nv_bfloat16 g_Xhi[MTOT*EMBED];            // x split  [m][k]
__device__ __nv_bfloat16 g_Xlo[MTOT*EMBED];
__device__ __nv_bfloat16 g_Whi[3*EMBED*EMBED];         // W split  [which][n][k]
__device__ __nv_bfloat16 g_Wlo[3*EMBED*EMBED];
__device__ __nv_bfloat16 g_Qhi[MTOT*EMBED];            // natural [b,s,h,d]
__device__ __nv_bfloat16 g_Qlo[MTOT*EMBED];
__device__ __nv_bfloat16 g_Khi[MTOT*EMBED];
__device__ __nv_bfloat16 g_Klo[MTOT*EMBED];
__device__ __nv_bfloat16 g_Vnhi[MTOT*EMBED];           // V natural
__device__ __nv_bfloat16 g_Vnlo[MTOT*EMBED];
__device__ __nv_bfloat16 g_Vthi[MTOT*EMBED];           // V transposed [b,h,d,s]
__device__ __nv_bfloat16 g_Vtlo[MTOT*EMBED];
__device__ uint32_t g_mbits[SEQ*SEQ/32];               // mask bitset, 2 MB

// ---------------------------------------------------------------------------
// helpers
// ---------------------------------------------------------------------------
__device__ __forceinline__ void bfsplit(float f, uint16_t& h, uint16_t& l) {
    __nv_bfloat16 hb = __float2bfloat16_rn(f);
    float fh = __bfloat162float(hb);
    __nv_bfloat16 lb = __float2bfloat16_rn(f - fh);
    h = __bfloat16_as_ushort(hb);
    l = __bfloat16_as_ushort(lb);
}
__device__ __forceinline__ uint32_t smem_to_u32(const void* p) {
    uint32_t a;
    asm("{ .reg .u64 t; cvta.to.shared.u64 t, %1; cvt.u32.u64 %0, t; }" : "=r"(a) : "l"(p));
    return a;
}
__device__ __forceinline__ void mma_bf16(float d[4], const uint32_t a[4],
                                         uint32_t b0, uint32_t b1) {
    asm volatile(
        "mma.sync.aligned.m16n8k16.row.col.f32.bf16.bf16.f32 "
        "{%0,%1,%2,%3}, {%4,%5,%6,%7}, {%8,%9}, {%0,%1,%2,%3};"
        : "+f"(d[0]), "+f"(d[1]), "+f"(d[2]), "+f"(d[3])
        : "r"(a[0]), "r"(a[1]), "r"(a[2]), "r"(a[3]), "r"(b0), "r"(b1));
}
__device__ __forceinline__ void ldm_x4(uint32_t& r0, uint32_t& r1,
                                       uint32_t& r2, uint32_t& r3, uint32_t addr) {
    asm volatile("ldmatrix.sync.aligned.m8n8.x4.shared.b16 {%0,%1,%2,%3}, [%4];"
        : "=r"(r0), "=r"(r1), "=r"(r2), "=r"(r3) : "r"(addr));
}
#define CP_ASYNC16(dst, src) \
    asm volatile("cp.async.cg.shared.global [%0], [%1], 16;" :: "r"(dst), "l"(src))
#define CP_COMMIT() asm volatile("cp.async.commit_group;" ::: "memory")
#define CP_WAIT(n)  asm volatile("cp.async.wait_group %0;" :: "n"(n) : "memory")

// ---------------------------------------------------------------------------
// Kernel 0: pack mask to bits — coalesced (ballot).
// ---------------------------------------------------------------------------
__global__ __launch_bounds__(256) void maskpack_kernel(const int* __restrict__ mask) {
    size_t i = (size_t)blockIdx.x*blockDim.x + threadIdx.x;
    int v = mask[i];
    uint32_t bits = __ballot_sync(0xffffffffu, v != 0);
    if ((threadIdx.x & 31) == 0) g_mbits[i >> 5] = bits;
}

// ---------------------------------------------------------------------------
// Kernel 0b/0c: split x and W into bf16 hi/lo.
// ---------------------------------------------------------------------------
__global__ __launch_bounds__(256) void splitx_kernel(const float* __restrict__ x) {
    size_t i = ((size_t)blockIdx.x*blockDim.x + threadIdx.x) * 4;
    float4 v = *(const float4*)&x[i];
    uint16_t h0,l0,h1,l1,h2,l2,h3,l3;
    bfsplit(v.x,h0,l0); bfsplit(v.y,h1,l1); bfsplit(v.z,h2,l2); bfsplit(v.w,h3,l3);
    *(uint32_t*)&g_Xhi[i]   = (uint32_t)h0 | ((uint32_t)h1 << 16);
    *(uint32_t*)&g_Xhi[i+2] = (uint32_t)h2 | ((uint32_t)h3 << 16);
    *(uint32_t*)&g_Xlo[i]   = (uint32_t)l0 | ((uint32_t)l1 << 16);
    *(uint32_t*)&g_Xlo[i+2] = (uint32_t)l2 | ((uint32_t)l3 << 16);
}
__global__ __launch_bounds__(256) void splitw_kernel(
    const float* __restrict__ Wq, const float* __restrict__ Wk,
    const float* __restrict__ Wv)
{
    size_t t = (size_t)blockIdx.x*blockDim.x + threadIdx.x;
    int which = (int)(t / (EMBED*EMBED/4));
    size_t off = (t % (EMBED*EMBED/4)) * 4;
    const float* W = (which==0) ? Wq : ((which==1) ? Wk : Wv);
    float4 v = *(const float4*)&W[off];
    uint16_t h0,l0,h1,l1,h2,l2,h3,l3;
    bfsplit(v.x,h0,l0); bfsplit(v.y,h1,l1); bfsplit(v.z,h2,l2); bfsplit(v.w,h3,l3);
    size_t d = (size_t)which*EMBED*EMBED + off;
    *(uint32_t*)&g_Whi[d]   = (uint32_t)h0 | ((uint32_t)h1 << 16);
    *(uint32_t*)&g_Whi[d+2] = (uint32_t)h2 | ((uint32_t)h3 << 16);
    *(uint32_t*)&g_Wlo[d]   = (uint32_t)l0 | ((uint32_t)l1 << 16);
    *(uint32_t*)&g_Wlo[d+2] = (uint32_t)l2 | ((uint32_t)l3 << 16);
}

// ---------------------------------------------------------------------------
// Kernel 1: projection via warp MMA (bf16 3-term split), double-buffered.
// y = x @ W^T + b.  CTA 256 thr = 8 warps, BM=128 (warp m16), BN=64, KC=64.
// ---------------------------------------------------------------------------
#define PP 72                         // smem pitch (bf16)
#define PROJ_SA (128*PP*2)            // 18432 B per A matrix
#define PROJ_SB (64*PP*2)             // 9216 B per B matrix
#define PROJ_STAGE (2*PROJ_SA + 2*PROJ_SB)   // 55296 B
#define PROJ_SMEM (2*PROJ_STAGE)             // 110592 B

__global__ __launch_bounds__(256) void proj_mma_kernel(
    const float* __restrict__ bq, const float* __restrict__ bk,
    const float* __restrict__ bv)
{
    extern __shared__ char dsm[];
    const uint32_t sbase = smem_to_u32(dsm);
    const uint32_t sAhi = 0, sAlo = PROJ_SA, sBhi = 2*PROJ_SA, sBlo = 2*PROJ_SA + PROJ_SB;

    const int which = blockIdx.z;
    const __nv_bfloat16* __restrict__ Bh = g_Whi + (size_t)which*EMBED*EMBED;
    const __nv_bfloat16* __restrict__ Bl = g_Wlo + (size_t)which*EMBED*EMBED;
    const float* __restrict__ bias = (which==0) ? bq : ((which==1) ? bk : bv);
    __nv_bfloat16* yhi = (which==0) ? g_Qhi : ((which==1) ? g_Khi : g_Vnhi);
    __nv_bfloat16* ylo = (which==0) ? g_Qlo : ((which==1) ? g_Klo : g_Vnlo);

    const int tid  = threadIdx.x;
    const int lane = tid & 31;
    const int warp = tid >> 5;
    const int g    = lane >> 2;
    const int ti   = lane & 3;
    const int m0 = blockIdx.y * 128;
    const int n0 = blockIdx.x * 64;

    const int lt = lane >> 3, lrow = lane & 7;
    const uint32_t offA = (uint32_t)(((lt&1)*8 + lrow)*PP + (lt>>1)*8) * 2;
    const uint32_t offB = (uint32_t)(((lt>>1)*8 + lrow)*PP + (lt&1)*8) * 2;
    const int sr = tid >> 3;            // A staging row (0..31, 4 passes)
    const int scc = (tid & 7) * 8;      // staging col

    float C[8][4];
    #pragma unroll
    for (int i = 0; i < 8; i++)
        #pragma unroll
        for (int j = 0; j < 4; j++) C[i][j] = 0.f;

    // prologue: stage kc=0 into buffer 0
    #pragma unroll
    for (int p = 0; p < 4; p++) {
        int r = sr + p*32;
        uint32_t db = sbase + (uint32_t)((r*PP + scc)*2);
        CP_ASYNC16(db + sAhi, &g_Xhi[(size_t)(m0+r)*EMBED + scc]);
        CP_ASYNC16(db + sAlo, &g_Xlo[(size_t)(m0+r)*EMBED + scc]);
    }
    #pragma unroll
    for (int p = 0; p < 2; p++) {
        int r = sr + p*32;
        uint32_t db = sbase + (uint32_t)((r*PP + scc)*2);
        CP_ASYNC16(db + sBhi, &Bh[(size_t)(n0+r)*EMBED + scc]);
        CP_ASYNC16(db + sBlo, &Bl[(size_t)(n0+r)*EMBED + scc]);
    }
    CP_COMMIT();

    for (int ki = 0; ki < 8; ki++) {
        if (ki + 1 < 8) {
            const int kn = (ki + 1) * 64;
            uint32_t bb = sbase + ((ki+1)&1)*PROJ_STAGE;
            #pragma unroll
            for (int p = 0; p < 4; p++) {
                int r = sr + p*32;
                uint32_t db = bb + (uint32_t)((r*PP + scc)*2);
                CP_ASYNC16(db + sAhi, &g_Xhi[(size_t)(m0+r)*EMBED + kn + scc]);
                CP_ASYNC16(db + sAlo, &g_Xlo[(size_t)(m0+r)*EMBED + kn + scc]);
            }
            #pragma unroll
            for (int p = 0; p < 2; p++) {
                int r = sr + p*32;
                uint32_t db = bb + (uint32_t)((r*PP + scc)*2);
                CP_ASYNC16(db + sBhi, &Bh[(size_t)(n0+r)*EMBED + kn + scc]);
                CP_ASYNC16(db + sBlo, &Bl[(size_t)(n0+r)*EMBED + kn + scc]);
            }
            CP_COMMIT();
            CP_WAIT(1);
        } else {
            CP_WAIT(0);
        }
        __syncthreads();

        const uint32_t ub = sbase + (ki&1)*PROJ_STAGE;
        const uint32_t aA = ub + (uint32_t)(warp*16*PP*2);
        #pragma unroll
        for (int ks = 0; ks < 4; ks++) {
            uint32_t ah[4], al[4];
            ldm_x4(ah[0],ah[1],ah[2],ah[3], aA + sAhi + offA + ks*32);
            ldm_x4(al[0],al[1],al[2],al[3], aA + sAlo + offA + ks*32);
            #pragma unroll
            for (int nb = 0; nb < 4; nb++) {
                uint32_t off = (uint32_t)(nb*16*PP*2 + ks*32);
                uint32_t h0,h1,h2,h3, l0,l1,l2,l3;
                ldm_x4(h0,h1,h2,h3, ub + sBhi + offB + off);
                ldm_x4(l0,l1,l2,l3, ub + sBlo + offB + off);
                mma_bf16(C[2*nb],   ah, h0, h1);
                mma_bf16(C[2*nb],   ah, l0, l1);
                mma_bf16(C[2*nb],   al, h0, h1);
                mma_bf16(C[2*nb+1], ah, h2, h3);
                mma_bf16(C[2*nb+1], ah, l2, l3);
                mma_bf16(C[2*nb+1], al, h2, h3);
            }
        }
        __syncthreads();
    }

    const int mrow0 = m0 + warp*16 + g;
    const int mrow1 = mrow0 + 8;
    #pragma unroll
    for (int ns = 0; ns < 8; ns++) {
        int n = n0 + ns*8 + ti*2;
        float b0 = __ldg(&bias[n]), b1 = __ldg(&bias[n+1]);
        uint16_t h0,l0,h1,l1,h2,l2,h3,l3;
        bfsplit(C[ns][0] + b0, h0, l0);
        bfsplit(C[ns][1] + b1, h1, l1);
        bfsplit(C[ns][2] + b0, h2, l2);
        bfsplit(C[ns][3] + b1, h3, l3);
        *(uint32_t*)&yhi[(size_t)mrow0*EMBED + n] = (uint32_t)h0 | ((uint32_t)h1 << 16);
        *(uint32_t*)&ylo[(size_t)mrow0*EMBED + n] = (uint32_t)l0 | ((uint32_t)l1 << 16);
        *(uint32_t*)&yhi[(size_t)mrow1*EMBED + n] = (uint32_t)h2 | ((uint32_t)h3 << 16);
        *(uint32_t*)&ylo[(size_t)mrow1*EMBED + n] = (uint32_t)l2 | ((uint32_t)l3 << 16);
    }
}

// ---------------------------------------------------------------------------
// Kernel 1b: transpose V natural [b,s,h,d] -> [b,h,d,s], smem tiled.
// ---------------------------------------------------------------------------
__global__ __launch_bounds__(256) void vtrans_kernel()
{
    __shared__ uint16_t th[64][65];
    __shared__ uint16_t tl[64][65];
    const int tid = threadIdx.x;
    const int bh = blockIdx.y;
    const int b = bh >> 3, h = bh & 7;
    const int s0 = blockIdx.x * 64;

    {
        int s = tid >> 2, dseg = (tid & 3) * 16;
        size_t src = ((size_t)(b*SEQ + s0 + s))*EMBED + h*HD + dseg;
        uint4 v0 = *(const uint4*)&g_Vnhi[src];
        uint4 v1 = *(const uint4*)&g_Vnhi[src + 8];
        uint4 w0 = *(const uint4*)&g_Vnlo[src];
        uint4 w1 = *(const uint4*)&g_Vnlo[src + 8];
        uint32_t hv[8] = {v0.x,v0.y,v0.z,v0.w, v1.x,v1.y,v1.z,v1.w};
        uint32_t lv[8] = {w0.x,w0.y,w0.z,w0.w, w1.x,w1.y,w1.z,w1.w};
        #pragma unroll
        for (int i = 0; i < 8; i++) {
            th[s][dseg + 2*i]     = (uint16_t)(hv[i] & 0xffff);
            th[s][dseg + 2*i + 1] = (uint16_t)(hv[i] >> 16);
            tl[s][dseg + 2*i]     = (uint16_t)(lv[i] & 0xffff);
            tl[s][dseg + 2*i + 1] = (uint16_t)(lv[i] >> 16);
        }
    }
    __syncthreads();
    {
        int d = tid >> 2, sseg = (tid & 3) * 16;
        uint32_t hv[8], lv[8];
        #pragma unroll
        for (int i = 0; i < 8; i++) {
            hv[i] = (uint32_t)th[sseg + 2*i][d] | ((uint32_t)th[sseg + 2*i + 1][d] << 16);
            lv[i] = (uint32_t)tl[sseg + 2*i][d] | ((uint32_t)tl[sseg + 2*i + 1][d] << 16);
        }
        size_t dst = ((size_t)bh*HD + d)*SEQ + s0 + sseg;
        *(uint4*)&g_Vthi[dst]     = make_uint4(hv[0],hv[1],hv[2],hv[3]);
        *(uint4*)&g_Vthi[dst + 8] = make_uint4(hv[4],hv[5],hv[6],hv[7]);
        *(uint4*)&g_Vtlo[dst]     = make_uint4(lv[0],lv[1],lv[2],lv[3]);
        *(uint4*)&g_Vtlo[dst + 8] = make_uint4(lv[4],lv[5],lv[6],lv[7]);
    }
}

// ---------------------------------------------------------------------------
// Kernel 2: warp-MMA flash attention. BM=128 q rows (8 warps, 256 thr),
// BN=64 kv per tile. Halves K/V L2 traffic + staging vs BM=64.
// ---------------------------------------------------------------------------
#define SMP 72
#define TILE_B (64*SMP*2)
#define BUF_B  (4*TILE_B)
#define ATTN_SMEM (2*BUF_B)

__global__ __launch_bounds__(256) void attn_mma_kernel(float* __restrict__ out)
{
    extern __shared__ char dsm[];
    const uint32_t sbase = smem_to_u32(dsm);

    const int tid  = threadIdx.x;
    const int lane = tid & 31;
    const int warp = tid >> 5;
    const int g    = lane >> 2;
    const int ti   = lane & 3;
    const int bh   = blockIdx.y;
    const int b    = bh >> 3, h = bh & 7;
    const int q0   = blockIdx.x*128 + warp*16;

    const size_t qkbase = ((size_t)b*SEQ)*EMBED + h*HD;
    const __nv_bfloat16* Qh = g_Qhi + qkbase;
    const __nv_bfloat16* Ql = g_Qlo + qkbase;
    const __nv_bfloat16* Kh = g_Khi + qkbase;
    const __nv_bfloat16* Kl = g_Klo + qkbase;
    const __nv_bfloat16* Vh = g_Vthi + (size_t)bh*HD*SEQ;
    const __nv_bfloat16* Vl = g_Vtlo + (size_t)bh*HD*SEQ;

    uint32_t qh[4][4], ql[4][4];
    #pragma unroll
    for (int ks = 0; ks < 4; ks++)
        #pragma unroll
        for (int r = 0; r < 4; r++) {
            int row = q0 + g + (r & 1)*8;
            int k   = ks*16 + ti*2 + (r >> 1)*8;
            qh[ks][r] = *(const uint32_t*)&Qh[(size_t)row*EMBED + k];
            ql[ks][r] = *(const uint32_t*)&Ql[(size_t)row*EMBED + k];
        }

    float O[8][4];
    #pragma unroll
    for (int i = 0; i < 8; i++)
        #pragma unroll
        for (int j = 0; j < 4; j++) O[i][j] = 0.f;
    float ls0 = 0.f, ls1 = 0.f;

    const int sr = tid >> 3;            // 0..31: staging covers 64 rows in 2 passes
    const int sc = (tid & 7) * 8;
    const int lt = lane >> 3, lrow = lane & 7;
    const uint32_t offB = (uint32_t)(((lt>>1)*8 + lrow)*SMP + (lt&1)*8) * 2;

    const int row0 = q0 + g, row1 = row0 + 8;

    #pragma unroll
    for (int p = 0; p < 2; p++) {
        int r = sr + p*32;
        uint32_t db = sbase + (uint32_t)((r*SMP + sc)*2);
        CP_ASYNC16(db + 0*TILE_B, &Kh[(size_t)r*EMBED + sc]);
        CP_ASYNC16(db + 1*TILE_B, &Kl[(size_t)r*EMBED + sc]);
        CP_ASYNC16(db + 2*TILE_B, &Vh[(size_t)r*SEQ + sc]);
        CP_ASYNC16(db + 3*TILE_B, &Vl[(size_t)r*SEQ + sc]);
    }
    CP_COMMIT();

    for (int jt = 0; jt < 64; jt++) {
        const int j0 = jt * 64;
        if (jt + 1 < 64) {
            const int jn = j0 + 64;
            uint32_t bbase = sbase + ((jt+1)&1)*BUF_B;
            #pragma unroll
            for (int p = 0; p < 2; p++) {
                int r = sr + p*32;
                uint32_t db = bbase + (uint32_t)((r*SMP + sc)*2);
                CP_ASYNC16(db + 0*TILE_B, &Kh[(size_t)(jn+r)*EMBED + sc]);
                CP_ASYNC16(db + 1*TILE_B, &Kl[(size_t)(jn+r)*EMBED + sc]);
                CP_ASYNC16(db + 2*TILE_B, &Vh[(size_t)r*SEQ + jn + sc]);
                CP_ASYNC16(db + 3*TILE_B, &Vl[(size_t)r*SEQ + jn + sc]);
            }
            CP_COMMIT();
            CP_WAIT(1);
        } else {
            CP_WAIT(0);
        }
        __syncthreads();

        const uint32_t ub = sbase + (jt&1)*BUF_B;
        const uint32_t aKh = ub + 0*TILE_B + offB;
        const uint32_t aKl = ub + 1*TILE_B + offB;
        const uint32_t aVh = ub + 2*TILE_B + offB;
        const uint32_t aVl = ub + 3*TILE_B + offB;

        float S[8][4];
        #pragma unroll
        for (int i = 0; i < 8; i++)
            #pragma unroll
            for (int j = 0; j < 4; j++) S[i][j] = 0.f;

        #pragma unroll
        for (int ks = 0; ks < 4; ks++)
            #pragma unroll
            for (int nb = 0; nb < 4; nb++) {
                uint32_t off = (uint32_t)(nb*16*SMP*2 + ks*32);
                uint32_t h0,h1,h2,h3, l0,l1,l2,l3;
                ldm_x4(h0,h1,h2,h3, aKh + off);
                ldm_x4(l0,l1,l2,l3, aKl + off);
                mma_bf16(S[2*nb],   qh[ks], h0, h1);
                mma_bf16(S[2*nb],   qh[ks], l0, l1);
                mma_bf16(S[2*nb],   ql[ks], h0, h1);
                mma_bf16(S[2*nb+1], qh[ks], h2, h3);
                mma_bf16(S[2*nb+1], qh[ks], l2, l3);
                mma_bf16(S[2*nb+1], ql[ks], h2, h3);
            }

        uint64_t mb0 = *(const uint64_t*)&g_mbits[(size_t)row0*(SEQ/32) + (j0>>5)];
        uint64_t mb1 = *(const uint64_t*)&g_mbits[(size_t)row1*(SEQ/32) + (j0>>5)];
        #pragma unroll
        for (int ns = 0; ns < 8; ns++) {
            int c = ns*8 + ti*2;
            float b00 = ((mb0 >> c) & 1ull)     ? -10000.f : 0.f;
            float b01 = ((mb0 >> (c+1)) & 1ull) ? -10000.f : 0.f;
            float b10 = ((mb1 >> c) & 1ull)     ? -10000.f : 0.f;
            float b11 = ((mb1 >> (c+1)) & 1ull) ? -10000.f : 0.f;
            S[ns][0] = __expf(fmaf(S[ns][0], 0.125f, b00));
            S[ns][1] = __expf(fmaf(S[ns][1], 0.125f, b01));
            S[ns][2] = __expf(fmaf(S[ns][2], 0.125f, b10));
            S[ns][3] = __expf(fmaf(S[ns][3], 0.125f, b11));
            ls0 += S[ns][0] + S[ns][1];
            ls1 += S[ns][2] + S[ns][3];
        }

        uint32_t ph[4][4], pl[4][4];
        #pragma unroll
        for (int kp = 0; kp < 4; kp++)
            #pragma unroll
            for (int r = 0; r < 4; r++) {
                int nsrc = 2*kp + (r >> 1);
                int e = (r & 1)*2;
                float p0 = S[nsrc][e], p1 = S[nsrc][e+1];
                __nv_bfloat162 hb = __floats2bfloat162_rn(p0, p1);
                float f0 = __bfloat162float(hb.x), f1 = __bfloat162float(hb.y);
                __nv_bfloat162 lb = __floats2bfloat162_rn(p0 - f0, p1 - f1);
                uint32_t uh, ul;
                memcpy(&uh, &hb, 4); memcpy(&ul, &lb, 4);
                ph[kp][r] = uh; pl[kp][r] = ul;
            }

        #pragma unroll
        for (int kp = 0; kp < 4; kp++)
            #pragma unroll
            for (int db = 0; db < 4; db++) {
                uint32_t off = (uint32_t)(db*16*SMP*2 + kp*32);
                uint32_t h0,h1,h2,h3, l0,l1,l2,l3;
                ldm_x4(h0,h1,h2,h3, aVh + off);
                ldm_x4(l0,l1,l2,l3, aVl + off);
                mma_bf16(O[2*db],   ph[kp], h0, h1);
                mma_bf16(O[2*db],   ph[kp], l0, l1);
                mma_bf16(O[2*db],   pl[kp], h0, h1);
                mma_bf16(O[2*db+1], ph[kp], h2, h3);
                mma_bf16(O[2*db+1], ph[kp], l2, l3);
                mma_bf16(O[2*db+1], pl[kp], h2, h3);
            }
        __syncthreads();
    }

    ls0 += __shfl_xor_sync(0xffffffffu, ls0, 1);
    ls0 += __shfl_xor_sync(0xffffffffu, ls0, 2);
    ls1 += __shfl_xor_sync(0xffffffffu, ls1, 1);
    ls1 += __shfl_xor_sync(0xffffffffu, ls1, 2);
    float i0 = 1.f/ls0, i1 = 1.f/ls1;

    float* o0 = out + ((size_t)b*SEQ + row0)*EMBED + h*HD;
    float* o1 = out + ((size_t)b*SEQ + row1)*EMBED + h*HD;
    #pragma unroll
    for (int ds = 0; ds < 8; ds++) {
        int d = ds*8 + ti*2;
        float2 v0 = make_float2(O[ds][0]*i0, O[ds][1]*i0);
        float2 v1 = make_float2(O[ds][2]*i1, O[ds][3]*i1);
        *(float2*)&o0[d] = v0;
        *(float2*)&o1[d] = v1;
    }
}

extern "C" void kernel_launch(void* const* d_in, const int* in_sizes, int n_in,
                              void* d_out, int out_size)
{
    const float* x    = (const float*)d_in[0];
    const int*   mask = (const int*)  d_in[1];
    const float* Wq   = (const float*)d_in[2];
    const float* bq   = (const float*)d_in[3];
    const float* Wk   = (const float*)d_in[4];
    const float* bk   = (const float*)d_in[5];
    const float* Wv   = (const float*)d_in[6];
    const float* bv   = (const float*)d_in[7];
    float* out = (float*)d_out;

    cudaFuncSetAttribute(attn_mma_kernel,
                         cudaFuncAttributeMaxDynamicSharedMemorySize, ATTN_SMEM);
    cudaFuncSetAttribute(proj_mma_kernel,
                         cudaFuncAttributeMaxDynamicSharedMemorySize, PROJ_SMEM);

    maskpack_kernel<<<(SEQ*SEQ)/256, 256>>>(mask);
    splitx_kernel<<<(MTOT*EMBED/4)/256, 256>>>(x);
    splitw_kernel<<<(3*EMBED*EMBED/4)/256, 256>>>(Wq, Wk, Wv);

    dim3 pgrid(EMBED/64, MTOT/128, 3);   // (8, 64, 3)
    proj_mma_kernel<<<pgrid, 256, PROJ_SMEM>>>(bq, bk, bv);

    dim3 vgrid(SEQ/64, BATCH*NHEADS);
    vtrans_kernel<<<vgrid, 256>>>();

    dim3 agrid(SEQ/128, BATCH*NHEADS);   // (32, 16)
    attn_mma_kernel<<<agrid, 256, ATTN_SMEM>>>(out);
}

// round 12
// speedup vs baseline: 1.1846x; 1.1846x over previous
#include <cuda_runtime.h>
#include <cuda_bf16.h>
#include <math.h>
#include <stdint.h>
#include <string.h>

#define EMBED 512
#define NHEADS 8
#define HD 64
#define BATCH 2
#define SEQ 4096
#define MTOT (BATCH*SEQ)

// bf16 hi/lo split tensors.
__device__ __nv_bfloat16 g_Xhi[MTOT*EMBED];            // x split  [m][k]
__device__ __nv_bfloat16 g_Xlo[MTOT*EMBED];
__device__ __nv_bfloat16 g_Whi[3*EMBED*EMBED];         // W split  [which][n][k]
__device__ __nv_bfloat16 g_Wlo[3*EMBED*EMBED];
__device__ __nv_bfloat16 g_Qhi[MTOT*EMBED];            // natural [b,s,h,d]
__device__ __nv_bfloat16 g_Qlo[MTOT*EMBED];
__device__ __nv_bfloat16 g_Khi[MTOT*EMBED];
__device__ __nv_bfloat16 g_Klo[MTOT*EMBED];
__device__ __nv_bfloat16 g_Vnhi[MTOT*EMBED];           // V natural
__device__ __nv_bfloat16 g_Vnlo[MTOT*EMBED];
__device__ __nv_bfloat16 g_Vthi[MTOT*EMBED];           // V transposed [b,h,d,s]
__device__ __nv_bfloat16 g_Vtlo[MTOT*EMBED];
__device__ uint32_t g_mbits[SEQ*SEQ/32];               // mask bitset, 2 MB

// ---------------------------------------------------------------------------
// helpers
// ---------------------------------------------------------------------------
__device__ __forceinline__ void bfsplit(float f, uint16_t& h, uint16_t& l) {
    __nv_bfloat16 hb = __float2bfloat16_rn(f);
    float fh = __bfloat162float(hb);
    __nv_bfloat16 lb = __float2bfloat16_rn(f - fh);
    h = __bfloat16_as_ushort(hb);
    l = __bfloat16_as_ushort(lb);
}
__device__ __forceinline__ uint32_t smem_to_u32(const void* p) {
    uint32_t a;
    asm("{ .reg .u64 t; cvta.to.shared.u64 t, %1; cvt.u32.u64 %0, t; }" : "=r"(a) : "l"(p));
    return a;
}
__device__ __forceinline__ void mma_bf16(float d[4], const uint32_t a[4],
                                         uint32_t b0, uint32_t b1) {
    asm volatile(
        "mma.sync.aligned.m16n8k16.row.col.f32.bf16.bf16.f32 "
        "{%0,%1,%2,%3}, {%4,%5,%6,%7}, {%8,%9}, {%0,%1,%2,%3};"
        : "+f"(d[0]), "+f"(d[1]), "+f"(d[2]), "+f"(d[3])
        : "r"(a[0]), "r"(a[1]), "r"(a[2]), "r"(a[3]), "r"(b0), "r"(b1));
}
__device__ __forceinline__ void ldm_x4(uint32_t& r0, uint32_t& r1,
                                       uint32_t& r2, uint32_t& r3, uint32_t addr) {
    asm volatile("ldmatrix.sync.aligned.m8n8.x4.shared.b16 {%0,%1,%2,%3}, [%4];"
        : "=r"(r0), "=r"(r1), "=r"(r2), "=r"(r3) : "r"(addr));
}
#define CP_ASYNC16(dst, src) \
    asm volatile("cp.async.cg.shared.global [%0], [%1], 16;" :: "r"(dst), "l"(src))
#define CP_COMMIT() asm volatile("cp.async.commit_group;" ::: "memory")
#define CP_WAIT(n)  asm volatile("cp.async.wait_group %0;" :: "n"(n) : "memory")

// ---------------------------------------------------------------------------
// Kernel 0: pack mask to bits — coalesced (ballot).
// ---------------------------------------------------------------------------
__global__ __launch_bounds__(256) void maskpack_kernel(const int* __restrict__ mask) {
    size_t i = (size_t)blockIdx.x*blockDim.x + threadIdx.x;
    int v = mask[i];
    uint32_t bits = __ballot_sync(0xffffffffu, v != 0);
    if ((threadIdx.x & 31) == 0) g_mbits[i >> 5] = bits;
}

// ---------------------------------------------------------------------------
// Kernel 0b/0c: split x and W into bf16 hi/lo.
// ---------------------------------------------------------------------------
__global__ __launch_bounds__(256) void splitx_kernel(const float* __restrict__ x) {
    size_t i = ((size_t)blockIdx.x*blockDim.x + threadIdx.x) * 4;
    float4 v = *(const float4*)&x[i];
    uint16_t h0,l0,h1,l1,h2,l2,h3,l3;
    bfsplit(v.x,h0,l0); bfsplit(v.y,h1,l1); bfsplit(v.z,h2,l2); bfsplit(v.w,h3,l3);
    *(uint32_t*)&g_Xhi[i]   = (uint32_t)h0 | ((uint32_t)h1 << 16);
    *(uint32_t*)&g_Xhi[i+2] = (uint32_t)h2 | ((uint32_t)h3 << 16);
    *(uint32_t*)&g_Xlo[i]   = (uint32_t)l0 | ((uint32_t)l1 << 16);
    *(uint32_t*)&g_Xlo[i+2] = (uint32_t)l2 | ((uint32_t)l3 << 16);
}
__global__ __launch_bounds__(256) void splitw_kernel(
    const float* __restrict__ Wq, const float* __restrict__ Wk,
    const float* __restrict__ Wv)
{
    size_t t = (size_t)blockIdx.x*blockDim.x + threadIdx.x;
    int which = (int)(t / (EMBED*EMBED/4));
    size_t off = (t % (EMBED*EMBED/4)) * 4;
    const float* W = (which==0) ? Wq : ((which==1) ? Wk : Wv);
    float4 v = *(const float4*)&W[off];
    uint16_t h0,l0,h1,l1,h2,l2,h3,l3;
    bfsplit(v.x,h0,l0); bfsplit(v.y,h1,l1); bfsplit(v.z,h2,l2); bfsplit(v.w,h3,l3);
    size_t d = (size_t)which*EMBED*EMBED + off;
    *(uint32_t*)&g_Whi[d]   = (uint32_t)h0 | ((uint32_t)h1 << 16);
    *(uint32_t*)&g_Whi[d+2] = (uint32_t)h2 | ((uint32_t)h3 << 16);
    *(uint32_t*)&g_Wlo[d]   = (uint32_t)l0 | ((uint32_t)l1 << 16);
    *(uint32_t*)&g_Wlo[d+2] = (uint32_t)l2 | ((uint32_t)l3 << 16);
}

// ---------------------------------------------------------------------------
// Kernel 1: projection via warp MMA (bf16 3-term split), single-buffered
// (verified round-7 config: 139.7us, tensor 52%).
// y = x @ W^T + b.  CTA 256 thr = 8 warps, BM=128 (warp m16), BN=64, KC=64.
// ---------------------------------------------------------------------------
#define PP 72                         // smem pitch (bf16)
#define PROJ_SA (128*PP*2)            // 18432 B per A matrix
#define PROJ_SB (64*PP*2)             // 9216 B per B matrix
#define PROJ_SMEM (2*PROJ_SA + 2*PROJ_SB)   // 55296 B

__global__ __launch_bounds__(256) void proj_mma_kernel(
    const float* __restrict__ bq, const float* __restrict__ bk,
    const float* __restrict__ bv)
{
    extern __shared__ char dsm[];
    const uint32_t sbase = smem_to_u32(dsm);
    const uint32_t sAhi = 0, sAlo = PROJ_SA, sBhi = 2*PROJ_SA, sBlo = 2*PROJ_SA + PROJ_SB;

    const int which = blockIdx.z;
    const __nv_bfloat16* __restrict__ Bh = g_Whi + (size_t)which*EMBED*EMBED;
    const __nv_bfloat16* __restrict__ Bl = g_Wlo + (size_t)which*EMBED*EMBED;
    const float* __restrict__ bias = (which==0) ? bq : ((which==1) ? bk : bv);
    __nv_bfloat16* yhi = (which==0) ? g_Qhi : ((which==1) ? g_Khi : g_Vnhi);
    __nv_bfloat16* ylo = (which==0) ? g_Qlo : ((which==1) ? g_Klo : g_Vnlo);

    const int tid  = threadIdx.x;
    const int lane = tid & 31;
    const int warp = tid >> 5;
    const int g    = lane >> 2;
    const int ti   = lane & 3;
    const int m0 = blockIdx.y * 128;
    const int n0 = blockIdx.x * 64;

    const int lt = lane >> 3, lrow = lane & 7;
    const uint32_t offA = (uint32_t)(((lt&1)*8 + lrow)*PP + (lt>>1)*8) * 2;
    const uint32_t offB = (uint32_t)(((lt>>1)*8 + lrow)*PP + (lt&1)*8) * 2;

    float C[8][4];
    #pragma unroll
    for (int i = 0; i < 8; i++)
        #pragma unroll
        for (int j = 0; j < 4; j++) C[i][j] = 0.f;

    for (int kc = 0; kc < EMBED; kc += 64) {
        // stage A (128x64 hi/lo) + B (64x64 hi/lo)
        #pragma unroll
        for (int p = 0; p < 4; p++) {
            int c = tid + p*256;
            int r = c >> 3, cc = (c & 7) * 8;
            uint32_t db = sbase + (uint32_t)((r*PP + cc)*2);
            CP_ASYNC16(db + sAhi, &g_Xhi[(size_t)(m0+r)*EMBED + kc + cc]);
            CP_ASYNC16(db + sAlo, &g_Xlo[(size_t)(m0+r)*EMBED + kc + cc]);
        }
        #pragma unroll
        for (int p = 0; p < 2; p++) {
            int c = tid + p*256;
            int r = c >> 3, cc = (c & 7) * 8;
            uint32_t db = sbase + (uint32_t)((r*PP + cc)*2);
            CP_ASYNC16(db + sBhi, &Bh[(size_t)(n0+r)*EMBED + kc + cc]);
            CP_ASYNC16(db + sBlo, &Bl[(size_t)(n0+r)*EMBED + kc + cc]);
        }
        CP_COMMIT();
        CP_WAIT(0);
        __syncthreads();

        const uint32_t aA = sbase + (uint32_t)(warp*16*PP*2);
        #pragma unroll
        for (int ks = 0; ks < 4; ks++) {
            uint32_t ah[4], al[4];
            ldm_x4(ah[0],ah[1],ah[2],ah[3], aA + sAhi + offA + ks*32);
            ldm_x4(al[0],al[1],al[2],al[3], aA + sAlo + offA + ks*32);
            #pragma unroll
            for (int nb = 0; nb < 4; nb++) {
                uint32_t off = (uint32_t)(nb*16*PP*2 + ks*32);
                uint32_t h0,h1,h2,h3, l0,l1,l2,l3;
                ldm_x4(h0,h1,h2,h3, sbase + sBhi + offB + off);
                ldm_x4(l0,l1,l2,l3, sbase + sBlo + offB + off);
                mma_bf16(C[2*nb],   ah, h0, h1);
                mma_bf16(C[2*nb],   ah, l0, l1);
                mma_bf16(C[2*nb],   al, h0, h1);
                mma_bf16(C[2*nb+1], ah, h2, h3);
                mma_bf16(C[2*nb+1], ah, l2, l3);
                mma_bf16(C[2*nb+1], al, h2, h3);
            }
        }
        __syncthreads();
    }

    // epilogue: +bias, split, write natural layout
    const int mrow0 = m0 + warp*16 + g;
    const int mrow1 = mrow0 + 8;
    #pragma unroll
    for (int ns = 0; ns < 8; ns++) {
        int n = n0 + ns*8 + ti*2;
        float b0 = __ldg(&bias[n]), b1 = __ldg(&bias[n+1]);
        uint16_t h0,l0,h1,l1,h2,l2,h3,l3;
        bfsplit(C[ns][0] + b0, h0, l0);
        bfsplit(C[ns][1] + b1, h1, l1);
        bfsplit(C[ns][2] + b0, h2, l2);
        bfsplit(C[ns][3] + b1, h3, l3);
        *(uint32_t*)&yhi[(size_t)mrow0*EMBED + n] = (uint32_t)h0 | ((uint32_t)h1 << 16);
        *(uint32_t*)&ylo[(size_t)mrow0*EMBED + n] = (uint32_t)l0 | ((uint32_t)l1 << 16);
        *(uint32_t*)&yhi[(size_t)mrow1*EMBED + n] = (uint32_t)h2 | ((uint32_t)h3 << 16);
        *(uint32_t*)&ylo[(size_t)mrow1*EMBED + n] = (uint32_t)l2 | ((uint32_t)l3 << 16);
    }
}

// ---------------------------------------------------------------------------
// Kernel 1b: transpose V natural [b,s,h,d] -> [b,h,d,s], smem tiled.
// ---------------------------------------------------------------------------
__global__ __launch_bounds__(256) void vtrans_kernel()
{
    __shared__ uint16_t th[64][65];
    __shared__ uint16_t tl[64][65];
    const int tid = threadIdx.x;
    const int bh = blockIdx.y;
    const int b = bh >> 3, h = bh & 7;
    const int s0 = blockIdx.x * 64;

    {
        int s = tid >> 2, dseg = (tid & 3) * 16;
        size_t src = ((size_t)(b*SEQ + s0 + s))*EMBED + h*HD + dseg;
        uint4 v0 = *(const uint4*)&g_Vnhi[src];
        uint4 v1 = *(const uint4*)&g_Vnhi[src + 8];
        uint4 w0 = *(const uint4*)&g_Vnlo[src];
        uint4 w1 = *(const uint4*)&g_Vnlo[src + 8];
        uint32_t hv[8] = {v0.x,v0.y,v0.z,v0.w, v1.x,v1.y,v1.z,v1.w};
        uint32_t lv[8] = {w0.x,w0.y,w0.z,w0.w, w1.x,w1.y,w1.z,w1.w};
        #pragma unroll
        for (int i = 0; i < 8; i++) {
            th[s][dseg + 2*i]     = (uint16_t)(hv[i] & 0xffff);
            th[s][dseg + 2*i + 1] = (uint16_t)(hv[i] >> 16);
            tl[s][dseg + 2*i]     = (uint16_t)(lv[i] & 0xffff);
            tl[s][dseg + 2*i + 1] = (uint16_t)(lv[i] >> 16);
        }
    }
    __syncthreads();
    {
        int d = tid >> 2, sseg = (tid & 3) * 16;
        uint32_t hv[8], lv[8];
        #pragma unroll
        for (int i = 0; i < 8; i++) {
            hv[i] = (uint32_t)th[sseg + 2*i][d] | ((uint32_t)th[sseg + 2*i + 1][d] << 16);
            lv[i] = (uint32_t)tl[sseg + 2*i][d] | ((uint32_t)tl[sseg + 2*i + 1][d] << 16);
        }
        size_t dst = ((size_t)bh*HD + d)*SEQ + s0 + sseg;
        *(uint4*)&g_Vthi[dst]     = make_uint4(hv[0],hv[1],hv[2],hv[3]);
        *(uint4*)&g_Vthi[dst + 8] = make_uint4(hv[4],hv[5],hv[6],hv[7]);
        *(uint4*)&g_Vtlo[dst]     = make_uint4(lv[0],lv[1],lv[2],lv[3]);
        *(uint4*)&g_Vtlo[dst + 8] = make_uint4(lv[4],lv[5],lv[6],lv[7]);
    }
}

// ---------------------------------------------------------------------------
// Kernel 2: warp-MMA flash attention. BM=64 (4 warps, 128 thr), BN=64.
// K double-buffered, V single-buffered (staged after PV, hides under next
// tile's S-MMA+softmax).  smem 55296 B -> 4 CTAs/SM -> 2 waves (was 3).
// cp.async group invariant at end of iter jt: pending = [A_{jt+1}, B_{jt+1}].
// ---------------------------------------------------------------------------
#define SMP 72
#define TILE1 (64*SMP*2)           // 9216 B, one 64x64 bf16 matrix
#define KSTRIDE (2*TILE1)          // Kh+Kl per K buffer
#define VHOFF (4*TILE1)            // 36864
#define VLOFF (5*TILE1)            // 46080
#define ATTN_SMEM (6*TILE1)        // 55296

__global__ __launch_bounds__(128, 4) void attn_mma_kernel(float* __restrict__ out)
{
    extern __shared__ char dsm[];
    const uint32_t sbase = smem_to_u32(dsm);

    const int tid  = threadIdx.x;
    const int lane = tid & 31;
    const int warp = tid >> 5;
    const int g    = lane >> 2;
    const int ti   = lane & 3;
    const int bh   = blockIdx.y;
    const int b    = bh >> 3, h = bh & 7;
    const int q0   = blockIdx.x*64 + warp*16;

    const size_t qkbase = ((size_t)b*SEQ)*EMBED + h*HD;
    const __nv_bfloat16* Qh = g_Qhi + qkbase;
    const __nv_bfloat16* Ql = g_Qlo + qkbase;
    const __nv_bfloat16* Kh = g_Khi + qkbase;
    const __nv_bfloat16* Kl = g_Klo + qkbase;
    const __nv_bfloat16* Vh = g_Vthi + (size_t)bh*HD*SEQ;
    const __nv_bfloat16* Vl = g_Vtlo + (size_t)bh*HD*SEQ;

    uint32_t qh[4][4], ql[4][4];
    #pragma unroll
    for (int ks = 0; ks < 4; ks++)
        #pragma unroll
        for (int r = 0; r < 4; r++) {
            int row = q0 + g + (r & 1)*8;
            int k   = ks*16 + ti*2 + (r >> 1)*8;
            qh[ks][r] = *(const uint32_t*)&Qh[(size_t)row*EMBED + k];
            ql[ks][r] = *(const uint32_t*)&Ql[(size_t)row*EMBED + k];
        }

    float O[8][4];
    #pragma unroll
    for (int i = 0; i < 8; i++)
        #pragma unroll
        for (int j = 0; j < 4; j++) O[i][j] = 0.f;
    float ls0 = 0.f, ls1 = 0.f;

    const int sr = tid >> 3;           // 0..15, 4 passes cover 64 rows
    const int sc = (tid & 7) * 8;
    const int lt = lane >> 3, lrow = lane & 7;
    const uint32_t offB = (uint32_t)(((lt>>1)*8 + lrow)*SMP + (lt&1)*8) * 2;

    const int row0 = q0 + g, row1 = row0 + 8;

    // prologue: K0 (group A_0), then V0 (group B_0)
    #pragma unroll
    for (int p = 0; p < 4; p++) {
        int r = sr + p*16;
        uint32_t db = sbase + (uint32_t)((r*SMP + sc)*2);
        CP_ASYNC16(db,          &Kh[(size_t)r*EMBED + sc]);
        CP_ASYNC16(db + TILE1,  &Kl[(size_t)r*EMBED + sc]);
    }
    CP_COMMIT();
    #pragma unroll
    for (int p = 0; p < 4; p++) {
        int r = sr + p*16;
        uint32_t db = sbase + (uint32_t)((r*SMP + sc)*2);
        CP_ASYNC16(db + VHOFF, &Vh[(size_t)r*SEQ + sc]);
        CP_ASYNC16(db + VLOFF, &Vl[(size_t)r*SEQ + sc]);
    }
    CP_COMMIT();

    for (int jt = 0; jt < 64; jt++) {
        const int j0 = jt * 64;
        if (jt < 63) {
            const int jn = j0 + 64;
            uint32_t kb = sbase + ((jt+1)&1)*KSTRIDE;
            #pragma unroll
            for (int p = 0; p < 4; p++) {
                int r = sr + p*16;
                uint32_t db = kb + (uint32_t)((r*SMP + sc)*2);
                CP_ASYNC16(db,         &Kh[(size_t)(jn+r)*EMBED + sc]);
                CP_ASYNC16(db + TILE1, &Kl[(size_t)(jn+r)*EMBED + sc]);
            }
            CP_COMMIT();
            CP_WAIT(2);      // pending: [B_jt, A_{jt+1}]; A_jt (K jt) done
        } else {
            CP_WAIT(1);      // pending: [B_63]; A_63 done
        }
        __syncthreads();

        const uint32_t ub = sbase + (jt&1)*KSTRIDE;
        const uint32_t aKh = ub + offB;
        const uint32_t aKl = ub + TILE1 + offB;

        float S[8][4];
        #pragma unroll
        for (int i = 0; i < 8; i++)
            #pragma unroll
            for (int j = 0; j < 4; j++) S[i][j] = 0.f;

        #pragma unroll
        for (int ks = 0; ks < 4; ks++)
            #pragma unroll
            for (int nb = 0; nb < 4; nb++) {
                uint32_t off = (uint32_t)(nb*16*SMP*2 + ks*32);
                uint32_t h0,h1,h2,h3, l0,l1,l2,l3;
                ldm_x4(h0,h1,h2,h3, aKh + off);
                ldm_x4(l0,l1,l2,l3, aKl + off);
                mma_bf16(S[2*nb],   qh[ks], h0, h1);
                mma_bf16(S[2*nb],   qh[ks], l0, l1);
                mma_bf16(S[2*nb],   ql[ks], h0, h1);
                mma_bf16(S[2*nb+1], qh[ks], h2, h3);
                mma_bf16(S[2*nb+1], qh[ks], l2, l3);
                mma_bf16(S[2*nb+1], ql[ks], h2, h3);
            }

        uint64_t mb0 = *(const uint64_t*)&g_mbits[(size_t)row0*(SEQ/32) + (j0>>5)];
        uint64_t mb1 = *(const uint64_t*)&g_mbits[(size_t)row1*(SEQ/32) + (j0>>5)];
        #pragma unroll
        for (int ns = 0; ns < 8; ns++) {
            int c = ns*8 + ti*2;
            float b00 = ((mb0 >> c) & 1ull)     ? -10000.f : 0.f;
            float b01 = ((mb0 >> (c+1)) & 1ull) ? -10000.f : 0.f;
            float b10 = ((mb1 >> c) & 1ull)     ? -10000.f : 0.f;
            float b11 = ((mb1 >> (c+1)) & 1ull) ? -10000.f : 0.f;
            S[ns][0] = __expf(fmaf(S[ns][0], 0.125f, b00));
            S[ns][1] = __expf(fmaf(S[ns][1], 0.125f, b01));
            S[ns][2] = __expf(fmaf(S[ns][2], 0.125f, b10));
            S[ns][3] = __expf(fmaf(S[ns][3], 0.125f, b11));
            ls0 += S[ns][0] + S[ns][1];
            ls1 += S[ns][2] + S[ns][3];
        }

        uint32_t ph[4][4], pl[4][4];
        #pragma unroll
        for (int kp = 0; kp < 4; kp++)
            #pragma unroll
            for (int r = 0; r < 4; r++) {
                int nsrc = 2*kp + (r >> 1);
                int e = (r & 1)*2;
                float p0 = S[nsrc][e], p1 = S[nsrc][e+1];
                __nv_bfloat162 hb = __floats2bfloat162_rn(p0, p1);
                float f0 = __bfloat162float(hb.x), f1 = __bfloat162float(hb.y);
                __nv_bfloat162 lb = __floats2bfloat162_rn(p0 - f0, p1 - f1);
                uint32_t uh, ul;
                memcpy(&uh, &hb, 4); memcpy(&ul, &lb, 4);
                ph[kp][r] = uh; pl[kp][r] = ul;
            }

        // wait for V(jt), keeping A_{jt+1} (K) in flight
        if (jt < 63) { CP_WAIT(1); } else { CP_WAIT(0); }
        __syncthreads();

        const uint32_t aVh = sbase + VHOFF + offB;
        const uint32_t aVl = sbase + VLOFF + offB;
        #pragma unroll
        for (int kp = 0; kp < 4; kp++)
            #pragma unroll
            for (int db = 0; db < 4; db++) {
                uint32_t off = (uint32_t)(db*16*SMP*2 + kp*32);
                uint32_t h0,h1,h2,h3, l0,l1,l2,l3;
                ldm_x4(h0,h1,h2,h3, aVh + off);
                ldm_x4(l0,l1,l2,l3, aVl + off);
                mma_bf16(O[2*db],   ph[kp], h0, h1);
                mma_bf16(O[2*db],   ph[kp], l0, l1);
                mma_bf16(O[2*db],   pl[kp], h0, h1);
                mma_bf16(O[2*db+1], ph[kp], h2, h3);
                mma_bf16(O[2*db+1], ph[kp], l2, l3);
                mma_bf16(O[2*db+1], pl[kp], h2, h3);
            }
        __syncthreads();   // all warps done reading V(jt)

        if (jt < 63) {
            const int jn = j0 + 64;
            #pragma unroll
            for (int p = 0; p < 4; p++) {
                int r = sr + p*16;
                uint32_t db = sbase + (uint32_t)((r*SMP + sc)*2);
                CP_ASYNC16(db + VHOFF, &Vh[(size_t)r*SEQ + jn + sc]);
                CP_ASYNC16(db + VLOFF, &Vl[(size_t)r*SEQ + jn + sc]);
            }
            CP_COMMIT();   // group B_{jt+1}
        }
    }

    ls0 += __shfl_xor_sync(0xffffffffu, ls0, 1);
    ls0 += __shfl_xor_sync(0xffffffffu, ls0, 2);
    ls1 += __shfl_xor_sync(0xffffffffu, ls1, 1);
    ls1 += __shfl_xor_sync(0xffffffffu, ls1, 2);
    float i0 = 1.f/ls0, i1 = 1.f/ls1;

    float* o0 = out + ((size_t)b*SEQ + row0)*EMBED + h*HD;
    float* o1 = out + ((size_t)b*SEQ + row1)*EMBED + h*HD;
    #pragma unroll
    for (int ds = 0; ds < 8; ds++) {
        int d = ds*8 + ti*2;
        float2 v0 = make_float2(O[ds][0]*i0, O[ds][1]*i0);
        float2 v1 = make_float2(O[ds][2]*i1, O[ds][3]*i1);
        *(float2*)&o0[d] = v0;
        *(float2*)&o1[d] = v1;
    }
}

extern "C" void kernel_launch(void* const* d_in, const int* in_sizes, int n_in,
                              void* d_out, int out_size)
{
    const float* x    = (const float*)d_in[0];
    const int*   mask = (const int*)  d_in[1];
    const float* Wq   = (const float*)d_in[2];
    const float* bq   = (const float*)d_in[3];
    const float* Wk   = (const float*)d_in[4];
    const float* bk   = (const float*)d_in[5];
    const float* Wv   = (const float*)d_in[6];
    const float* bv   = (const float*)d_in[7];
    float* out = (float*)d_out;

    cudaFuncSetAttribute(attn_mma_kernel,
                         cudaFuncAttributeMaxDynamicSharedMemorySize, ATTN_SMEM);
    cudaFuncSetAttribute(proj_mma_kernel,
                         cudaFuncAttributeMaxDynamicSharedMemorySize, PROJ_SMEM);

    maskpack_kernel<<<(SEQ*SEQ)/256, 256>>>(mask);
    splitx_kernel<<<(MTOT*EMBED/4)/256, 256>>>(x);
    splitw_kernel<<<(3*EMBED*EMBED/4)/256, 256>>>(Wq, Wk, Wv);

    dim3 pgrid(EMBED/64, MTOT/128, 3);   // (8, 64, 3)
    proj_mma_kernel<<<pgrid, 256, PROJ_SMEM>>>(bq, bk, bv);

    dim3 vgrid(SEQ/64, BATCH*NHEADS);
    vtrans_kernel<<<vgrid, 256>>>();

    dim3 agrid(SEQ/64, BATCH*NHEADS);    // (64, 16) — 1024 CTAs, 4/SM
    attn_mma_kernel<<<agrid, 128, ATTN_SMEM>>>(out);
}